// round 15
// baseline (speedup 1.0000x reference)
#include <cuda_runtime.h>

// Problem constants
static constexpr int Hd = 1024;   // hidden dim
static constexpr int Bn = 8192;   // batch
static constexpr int Mm = 4;      // modalities

// -------------------- device scratch (no allocation allowed) --------------------
__device__ float g_A [Hd * Hd];             // A  = Wq^T Wk            (4 MB)
__device__ float g_Wc[Hd * Hd];             // Wc = Wo Wv              (4 MB)
__device__ float g_u [Hd];                  // u[h] = sum_j bq[j] Wk[j,h]
__device__ float g_w [Hd];                  // w[o] = sum_j Wq[j,o] bk[j]
__device__ float g_bc[Hd];                  // bc   = Wo bv + bo
__device__ float g_c [1];                   // c    = bq . bk
__device__ float g_P [(size_t)Bn * Mm * Hd];// P[b,n,o] = sum_h A[o,h] f[b,n,h] (128 MB)
__device__ float g_G [(size_t)Bn * Hd];     // g[b,h]   = sum_n wgt[b,n] f[b,n,h] (32 MB)

// -------------------- generic SGEMM: C[m,n] = sum_k opA(m,k)*opB(n,k) --------------------
// opA(m,k) = A_KC ? A[m*K + k] : A[k*ldA + m]   (ldA passed as "ld")
// opB(n,k) = B_KC ? B[n*K + k] : B[k*ldB + n]
// Tiles: 128x128x16, 256 threads, 8x8 per thread, register-prefetch pipeline.
// All dims are multiples of 128 (M in {1024, 8192, 32768}, N=K=1024) -> no bounds checks.

static constexpr int BM = 128, BN = 128, BK = 16, PAD = 4;

template<bool KC>
__device__ __forceinline__ void tile_load(const float* __restrict__ g,
                                          int base, int K, int ld, int k0,
                                          int tid, float (&r)[8])
{
    if (KC) {
        // rows are K-contiguous: float4 along K
        const int k4  = tid & 3;     // which float4 of the 16 k's
        const int row = tid >> 2;    // 0..63
        const float* p = g + (size_t)(base + row) * K + k0 + k4 * 4;
        float4 v0 = *reinterpret_cast<const float4*>(p);
        float4 v1 = *reinterpret_cast<const float4*>(p + (size_t)64 * K);
        r[0] = v0.x; r[1] = v0.y; r[2] = v0.z; r[3] = v0.w;
        r[4] = v1.x; r[5] = v1.y; r[6] = v1.z; r[7] = v1.w;
    } else {
        // K is strided (row = k): float4 along m/n
        const int kk = tid >> 4;     // 0..15
        const int c4 = tid & 15;     // 0..15
        const float* p = g + (size_t)(k0 + kk) * ld + base + c4 * 4;
        float4 v0 = *reinterpret_cast<const float4*>(p);
        float4 v1 = *reinterpret_cast<const float4*>(p + 64);
        r[0] = v0.x; r[1] = v0.y; r[2] = v0.z; r[3] = v0.w;
        r[4] = v1.x; r[5] = v1.y; r[6] = v1.z; r[7] = v1.w;
    }
}

template<bool KC>
__device__ __forceinline__ void tile_store(float (&S)[BK][BM + PAD],
                                           int tid, const float (&r)[8])
{
    if (KC) {
        const int k4  = tid & 3;
        const int row = tid >> 2;
        #pragma unroll
        for (int c = 0; c < 4; c++) {
            S[k4 * 4 + c][row]      = r[c];
            S[k4 * 4 + c][row + 64] = r[4 + c];
        }
    } else {
        const int kk = tid >> 4;
        const int c4 = tid & 15;
        *reinterpret_cast<float4*>(&S[kk][c4 * 4])      = make_float4(r[0], r[1], r[2], r[3]);
        *reinterpret_cast<float4*>(&S[kk][64 + c4 * 4]) = make_float4(r[4], r[5], r[6], r[7]);
    }
}

__device__ __forceinline__ void mk_compute(const float (&As)[BK][BM + PAD],
                                           const float (&Bs)[BK][BN + PAD],
                                           float (&acc)[8][8], int ty, int tx)
{
    #pragma unroll
    for (int kk = 0; kk < BK; kk++) {
        float af[8], bf[8];
        *reinterpret_cast<float4*>(&af[0]) = *reinterpret_cast<const float4*>(&As[kk][ty * 8]);
        *reinterpret_cast<float4*>(&af[4]) = *reinterpret_cast<const float4*>(&As[kk][ty * 8 + 4]);
        *reinterpret_cast<float4*>(&bf[0]) = *reinterpret_cast<const float4*>(&Bs[kk][tx * 8]);
        *reinterpret_cast<float4*>(&bf[4]) = *reinterpret_cast<const float4*>(&Bs[kk][tx * 8 + 4]);
        #pragma unroll
        for (int i = 0; i < 8; i++)
            #pragma unroll
            for (int j = 0; j < 8; j++)
                acc[i][j] += af[i] * bf[j];
    }
}

template<bool A_KC, bool B_KC, bool BIAS>
__global__ __launch_bounds__(256, 2)
void sgemm_kernel(const float* __restrict__ Ag, const float* __restrict__ Bg,
                  float* __restrict__ Cg, const float* __restrict__ bias,
                  int M, int N, int K)
{
    __shared__ float As[BK][BM + PAD];
    __shared__ float Bs[BK][BN + PAD];

    const int tid = threadIdx.x;
    const int tx  = tid & 15;   // n-direction
    const int ty  = tid >> 4;   // m-direction
    const int m0  = blockIdx.y * BM;
    const int n0  = blockIdx.x * BN;

    float acc[8][8];
    #pragma unroll
    for (int i = 0; i < 8; i++)
        #pragma unroll
        for (int j = 0; j < 8; j++) acc[i][j] = 0.f;

    float ra[8], rb[8];

    // prologue: tile 0
    tile_load<A_KC>(Ag, m0, K, M, 0, tid, ra);
    tile_load<B_KC>(Bg, n0, K, N, 0, tid, rb);
    tile_store<A_KC>(As, tid, ra);
    tile_store<B_KC>(Bs, tid, rb);
    __syncthreads();

    for (int k0 = BK; k0 < K; k0 += BK) {
        // prefetch next tile to registers
        tile_load<A_KC>(Ag, m0, K, M, k0, tid, ra);
        tile_load<B_KC>(Bg, n0, K, N, k0, tid, rb);
        // compute on current smem tile
        mk_compute(As, Bs, acc, ty, tx);
        __syncthreads();
        tile_store<A_KC>(As, tid, ra);
        tile_store<B_KC>(Bs, tid, rb);
        __syncthreads();
    }
    mk_compute(As, Bs, acc, ty, tx);

    // epilogue
    float bz[8];
    #pragma unroll
    for (int j = 0; j < 8; j++)
        bz[j] = BIAS ? bias[n0 + tx * 8 + j] : 0.f;

    #pragma unroll
    for (int i = 0; i < 8; i++) {
        float* cp = Cg + (size_t)(m0 + ty * 8 + i) * N + n0 + tx * 8;
        float4 o0 = make_float4(acc[i][0] + bz[0], acc[i][1] + bz[1],
                                acc[i][2] + bz[2], acc[i][3] + bz[3]);
        float4 o1 = make_float4(acc[i][4] + bz[4], acc[i][5] + bz[5],
                                acc[i][6] + bz[6], acc[i][7] + bz[7]);
        *reinterpret_cast<float4*>(cp)     = o0;
        *reinterpret_cast<float4*>(cp + 4) = o1;
    }
}

// -------------------- small precompute kernels --------------------

// u[h] = sum_j bq[j]*Wk[j,h] ; w[h] = sum_j bk[j]*Wq[j,h]   (coalesced column sums)
__global__ void colsum_kernel(const float* __restrict__ Wk, const float* __restrict__ bq,
                              const float* __restrict__ Wq, const float* __restrict__ bk,
                              float* __restrict__ u, float* __restrict__ w)
{
    const int h = blockIdx.x * blockDim.x + threadIdx.x;
    float su = 0.f, sw = 0.f;
    for (int j = 0; j < Hd; j++) {
        su += bq[j] * Wk[(size_t)j * Hd + h];
        sw += bk[j] * Wq[(size_t)j * Hd + h];
    }
    u[h] = su;
    w[h] = sw;
}

// bc[o] = sum_j Wo[o,j]*bv[j] + bo[o]   (warp per row)
__global__ void bc_kernel(const float* __restrict__ Wo, const float* __restrict__ bv,
                          const float* __restrict__ bo, float* __restrict__ bc)
{
    const int o    = blockIdx.x * 8 + (threadIdx.x >> 5);
    const int lane = threadIdx.x & 31;
    float acc = 0.f;
    for (int j = lane; j < Hd; j += 32) acc += Wo[(size_t)o * Hd + j] * bv[j];
    #pragma unroll
    for (int off = 16; off > 0; off >>= 1) acc += __shfl_xor_sync(0xffffffffu, acc, off);
    if (lane == 0) bc[o] = acc + bo[o];
}

// c = bq . bk
__global__ void cdot_kernel(const float* __restrict__ bq, const float* __restrict__ bk,
                            float* __restrict__ out)
{
    __shared__ float sh[8];
    const int tid = threadIdx.x, lane = tid & 31, warp = tid >> 5;
    float acc = 0.f;
    for (int i = tid; i < Hd; i += 256) acc += bq[i] * bk[i];
    #pragma unroll
    for (int off = 16; off > 0; off >>= 1) acc += __shfl_xor_sync(0xffffffffu, acc, off);
    if (lane == 0) sh[warp] = acc;
    __syncthreads();
    if (tid == 0) {
        float s = 0.f;
        #pragma unroll
        for (int i = 0; i < 8; i++) s += sh[i];
        out[0] = s;
    }
}

// -------------------- attention + modality-mean combine --------------------
// Per batch b: scores[m][n] = (f_m.P_n + w.f_m + u.f_n + c)/32 * conf[b,m]
// attn = softmax_n(scores); wgt[n] = mean_m attn[m][n]; g[b] = sum_n wgt[n]*f_n
__global__ void attn_kernel(const float* __restrict__ F, const float* __restrict__ P,
                            const float* __restrict__ conf,
                            const float* __restrict__ u, const float* __restrict__ w,
                            const float* __restrict__ cptr,
                            float* __restrict__ G)
{
    const int b    = blockIdx.x;
    const int tid  = threadIdx.x;   // 128 threads
    const int warp = tid >> 5;      // 0..3 : modality m
    const int lane = tid & 31;

    const float* fb = F + (size_t)b * (Mm * Hd);
    const float* pb = P + (size_t)b * (Mm * Hd);

    __shared__ float s_s[4][4];
    __shared__ float s_wf[4], s_uf[4], s_wgt[4];

    // warp m keeps f_m in registers
    float fr[32];
    const float* fm = fb + warp * Hd;
    #pragma unroll
    for (int j = 0; j < 32; j++) fr[j] = fm[lane + j * 32];

    // raw quadratic scores: f_m . P_n
    #pragma unroll
    for (int n = 0; n < 4; n++) {
        const float* pn = pb + n * Hd;
        float acc = 0.f;
        #pragma unroll
        for (int j = 0; j < 32; j++) acc += fr[j] * pn[lane + j * 32];
        #pragma unroll
        for (int off = 16; off > 0; off >>= 1) acc += __shfl_xor_sync(0xffffffffu, acc, off);
        if (lane == 0) s_s[warp][n] = acc;
    }
    // linear terms: w.f_m and u.f_m
    {
        float aw = 0.f, au = 0.f;
        #pragma unroll
        for (int j = 0; j < 32; j++) {
            aw += fr[j] * w[lane + j * 32];
            au += fr[j] * u[lane + j * 32];
        }
        #pragma unroll
        for (int off = 16; off > 0; off >>= 1) {
            aw += __shfl_xor_sync(0xffffffffu, aw, off);
            au += __shfl_xor_sync(0xffffffffu, au, off);
        }
        if (lane == 0) { s_wf[warp] = aw; s_uf[warp] = au; }
    }
    __syncthreads();

    // tiny 4x4 softmax, row m handled by thread m
    if (tid < 4) {
        const int m = tid;
        const float cf = conf[(size_t)b * 4 + m];
        const float c0 = cptr[0];
        float l[4];
        #pragma unroll
        for (int n = 0; n < 4; n++)
            l[n] = (s_s[m][n] + s_wf[m] + s_uf[n] + c0) * (1.f / 32.f) * cf;
        float mx = fmaxf(fmaxf(l[0], l[1]), fmaxf(l[2], l[3]));
        float e[4], sum = 0.f;
        #pragma unroll
        for (int n = 0; n < 4; n++) { e[n] = expf(l[n] - mx); sum += e[n]; }
        const float inv = 1.f / sum;
        #pragma unroll
        for (int n = 0; n < 4; n++) s_s[m][n] = e[n] * inv;  // overwrite with attn
    }
    __syncthreads();
    if (tid < 4)
        s_wgt[tid] = 0.25f * (s_s[0][tid] + s_s[1][tid] + s_s[2][tid] + s_s[3][tid]);
    __syncthreads();

    const float w0 = s_wgt[0], w1 = s_wgt[1], w2 = s_wgt[2], w3 = s_wgt[3];
    float* gb = G + (size_t)b * Hd;
    for (int h = tid; h < Hd; h += 128)
        gb[h] = w0 * fb[h] + w1 * fb[Hd + h] + w2 * fb[2 * Hd + h] + w3 * fb[3 * Hd + h];
}

// -------------------- launch --------------------
extern "C" void kernel_launch(void* const* d_in, const int* in_sizes, int n_in,
                              void* d_out, int out_size)
{
    const float* F    = (const float*)d_in[0];  // [B, M, H]
    const float* conf = (const float*)d_in[1];  // [B, M, 1]
    const float* Wq   = (const float*)d_in[2];
    const float* bq   = (const float*)d_in[3];
    const float* Wk   = (const float*)d_in[4];
    const float* bk   = (const float*)d_in[5];
    const float* Wv   = (const float*)d_in[6];
    const float* bv   = (const float*)d_in[7];
    const float* Wo   = (const float*)d_in[8];
    const float* bo   = (const float*)d_in[9];
    float* out = (float*)d_out;                 // [B, H]

    float *pA, *pWc, *pu, *pw, *pbc, *pc, *pP, *pG;
    cudaGetSymbolAddress((void**)&pA,  g_A);
    cudaGetSymbolAddress((void**)&pWc, g_Wc);
    cudaGetSymbolAddress((void**)&pu,  g_u);
    cudaGetSymbolAddress((void**)&pw,  g_w);
    cudaGetSymbolAddress((void**)&pbc, g_bc);
    cudaGetSymbolAddress((void**)&pc,  g_c);
    cudaGetSymbolAddress((void**)&pP,  g_P);
    cudaGetSymbolAddress((void**)&pG,  g_G);

    const dim3 blk(256);

    // 1) A = Wq^T Wk : C[o,h] = sum_j Wq[j,o]*Wk[j,h]   (TN: both K-strided)
    sgemm_kernel<false, false, false><<<dim3(Hd / BN, Hd / BM), blk>>>(Wq, Wk, pA, nullptr, Hd, Hd, Hd);

    // 2) Wc = Wo Wv : C[o,h] = sum_j Wo[o,j]*Wv[j,h]    (NN)
    sgemm_kernel<true, false, false><<<dim3(Hd / BN, Hd / BM), blk>>>(Wo, Wv, pWc, nullptr, Hd, Hd, Hd);

    // 3) u, w column sums; 4) bc; 5) c
    colsum_kernel<<<Hd / 256, 256>>>(Wk, bq, Wq, bk, pu, pw);
    bc_kernel<<<Hd / 8, 256>>>(Wo, bv, bo, pbc);
    cdot_kernel<<<1, 256>>>(bq, bk, pc);

    // 6) P = F2d @ A^T : C[i,o] = sum_h F[i,h]*A[o,h]   (NT) — 68.7 GFLOP main GEMM
    sgemm_kernel<true, true, false><<<dim3(Hd / BN, (Bn * Mm) / BM), blk>>>(F, pA, pP, nullptr, Bn * Mm, Hd, Hd);

    // 7) per-batch 4x4 attention + weighted feature mean -> G
    attn_kernel<<<Bn, 128>>>(F, pP, conf, pu, pw, pc, pG);

    // 8) out = G @ Wc^T + bc                            (NT) — 17.2 GFLOP
    sgemm_kernel<true, true, true><<<dim3(Hd / BN, Bn / BM), blk>>>(pG, pWc, out, pbc, Bn, Hd, Hd);
}

// round 16
// speedup vs baseline: 1.0005x; 1.0005x over previous
#include <cuda_runtime.h>

// Problem constants
static constexpr int Hd = 1024;   // hidden dim
static constexpr int Bn = 8192;   // batch
static constexpr int Mm = 4;      // modalities

// -------------------- device scratch (no allocation allowed) --------------------
__device__ float g_A [Hd * Hd];             // A  = Wq^T Wk            (4 MB)
__device__ float g_Wc[Hd * Hd];             // Wc = Wo Wv              (4 MB)
__device__ float g_u [Hd];                  // u[h] = sum_j bq[j] Wk[j,h]
__device__ float g_w [Hd];                  // w[o] = sum_j Wq[j,o] bk[j]
__device__ float g_bc[Hd];                  // bc   = Wo bv + bo
__device__ float g_c [1];                   // c    = bq . bk
__device__ float g_P [(size_t)Bn * Mm * Hd];// P[b,n,o] = sum_h A[o,h] f[b,n,h] (128 MB)
__device__ float g_G [(size_t)Bn * Hd];     // g[b,h]   = sum_n wgt[b,n] f[b,n,h] (32 MB)

// -------------------- generic SGEMM: C[m,n] = sum_k opA(m,k)*opB(n,k) --------------------
// opA(m,k) = A_KC ? A[m*K + k] : A[k*ldA + m]   (ldA passed as "ld")
// opB(n,k) = B_KC ? B[n*K + k] : B[k*ldB + n]
// Tiles: 128x128x16, 256 threads, 8x8 per thread, register-prefetch pipeline.
// All dims are multiples of 128 (M in {1024, 8192, 32768}, N=K=1024) -> no bounds checks.

static constexpr int BM = 128, BN = 128, BK = 16, PAD = 4;

template<bool KC>
__device__ __forceinline__ void tile_load(const float* __restrict__ g,
                                          int base, int K, int ld, int k0,
                                          int tid, float (&r)[8])
{
    if (KC) {
        // rows are K-contiguous: float4 along K
        const int k4  = tid & 3;     // which float4 of the 16 k's
        const int row = tid >> 2;    // 0..63
        const float* p = g + (size_t)(base + row) * K + k0 + k4 * 4;
        float4 v0 = *reinterpret_cast<const float4*>(p);
        float4 v1 = *reinterpret_cast<const float4*>(p + (size_t)64 * K);
        r[0] = v0.x; r[1] = v0.y; r[2] = v0.z; r[3] = v0.w;
        r[4] = v1.x; r[5] = v1.y; r[6] = v1.z; r[7] = v1.w;
    } else {
        // K is strided (row = k): float4 along m/n
        const int kk = tid >> 4;     // 0..15
        const int c4 = tid & 15;     // 0..15
        const float* p = g + (size_t)(k0 + kk) * ld + base + c4 * 4;
        float4 v0 = *reinterpret_cast<const float4*>(p);
        float4 v1 = *reinterpret_cast<const float4*>(p + 64);
        r[0] = v0.x; r[1] = v0.y; r[2] = v0.z; r[3] = v0.w;
        r[4] = v1.x; r[5] = v1.y; r[6] = v1.z; r[7] = v1.w;
    }
}

template<bool KC>
__device__ __forceinline__ void tile_store(float (&S)[BK][BM + PAD],
                                           int tid, const float (&r)[8])
{
    if (KC) {
        const int k4  = tid & 3;
        const int row = tid >> 2;
        #pragma unroll
        for (int c = 0; c < 4; c++) {
            S[k4 * 4 + c][row]      = r[c];
            S[k4 * 4 + c][row + 64] = r[4 + c];
        }
    } else {
        const int kk = tid >> 4;
        const int c4 = tid & 15;
        *reinterpret_cast<float4*>(&S[kk][c4 * 4])      = make_float4(r[0], r[1], r[2], r[3]);
        *reinterpret_cast<float4*>(&S[kk][64 + c4 * 4]) = make_float4(r[4], r[5], r[6], r[7]);
    }
}

__device__ __forceinline__ void mk_compute(const float (&As)[BK][BM + PAD],
                                           const float (&Bs)[BK][BN + PAD],
                                           float (&acc)[8][8], int ty, int tx)
{
    #pragma unroll
    for (int kk = 0; kk < BK; kk++) {
        float af[8], bf[8];
        *reinterpret_cast<float4*>(&af[0]) = *reinterpret_cast<const float4*>(&As[kk][ty * 8]);
        *reinterpret_cast<float4*>(&af[4]) = *reinterpret_cast<const float4*>(&As[kk][ty * 8 + 4]);
        *reinterpret_cast<float4*>(&bf[0]) = *reinterpret_cast<const float4*>(&Bs[kk][tx * 8]);
        *reinterpret_cast<float4*>(&bf[4]) = *reinterpret_cast<const float4*>(&Bs[kk][tx * 8 + 4]);
        #pragma unroll
        for (int i = 0; i < 8; i++)
            #pragma unroll
            for (int j = 0; j < 8; j++)
                acc[i][j] += af[i] * bf[j];
    }
}

template<bool A_KC, bool B_KC, bool BIAS>
__global__ __launch_bounds__(256, 2)
void sgemm_kernel(const float* __restrict__ Ag, const float* __restrict__ Bg,
                  float* __restrict__ Cg, const float* __restrict__ bias,
                  int M, int N, int K)
{
    __shared__ float As[BK][BM + PAD];
    __shared__ float Bs[BK][BN + PAD];

    const int tid = threadIdx.x;
    const int tx  = tid & 15;   // n-direction
    const int ty  = tid >> 4;   // m-direction
    const int m0  = blockIdx.y * BM;
    const int n0  = blockIdx.x * BN;

    float acc[8][8];
    #pragma unroll
    for (int i = 0; i < 8; i++)
        #pragma unroll
        for (int j = 0; j < 8; j++) acc[i][j] = 0.f;

    float ra[8], rb[8];

    // prologue: tile 0
    tile_load<A_KC>(Ag, m0, K, M, 0, tid, ra);
    tile_load<B_KC>(Bg, n0, K, N, 0, tid, rb);
    tile_store<A_KC>(As, tid, ra);
    tile_store<B_KC>(Bs, tid, rb);
    __syncthreads();

    for (int k0 = BK; k0 < K; k0 += BK) {
        // prefetch next tile to registers
        tile_load<A_KC>(Ag, m0, K, M, k0, tid, ra);
        tile_load<B_KC>(Bg, n0, K, N, k0, tid, rb);
        // compute on current smem tile
        mk_compute(As, Bs, acc, ty, tx);
        __syncthreads();
        tile_store<A_KC>(As, tid, ra);
        tile_store<B_KC>(Bs, tid, rb);
        __syncthreads();
    }
    mk_compute(As, Bs, acc, ty, tx);

    // epilogue
    float bz[8];
    #pragma unroll
    for (int j = 0; j < 8; j++)
        bz[j] = BIAS ? bias[n0 + tx * 8 + j] : 0.f;

    #pragma unroll
    for (int i = 0; i < 8; i++) {
        float* cp = Cg + (size_t)(m0 + ty * 8 + i) * N + n0 + tx * 8;
        float4 o0 = make_float4(acc[i][0] + bz[0], acc[i][1] + bz[1],
                                acc[i][2] + bz[2], acc[i][3] + bz[3]);
        float4 o1 = make_float4(acc[i][4] + bz[4], acc[i][5] + bz[5],
                                acc[i][6] + bz[6], acc[i][7] + bz[7]);
        *reinterpret_cast<float4*>(cp)     = o0;
        *reinterpret_cast<float4*>(cp + 4) = o1;
    }
}

// -------------------- small precompute kernels --------------------

// u[h] = sum_j bq[j]*Wk[j,h] ; w[h] = sum_j bk[j]*Wq[j,h]   (coalesced column sums)
__global__ void colsum_kernel(const float* __restrict__ Wk, const float* __restrict__ bq,
                              const float* __restrict__ Wq, const float* __restrict__ bk,
                              float* __restrict__ u, float* __restrict__ w)
{
    const int h = blockIdx.x * blockDim.x + threadIdx.x;
    float su = 0.f, sw = 0.f;
    for (int j = 0; j < Hd; j++) {
        su += bq[j] * Wk[(size_t)j * Hd + h];
        sw += bk[j] * Wq[(size_t)j * Hd + h];
    }
    u[h] = su;
    w[h] = sw;
}

// bc[o] = sum_j Wo[o,j]*bv[j] + bo[o]   (warp per row)
__global__ void bc_kernel(const float* __restrict__ Wo, const float* __restrict__ bv,
                          const float* __restrict__ bo, float* __restrict__ bc)
{
    const int o    = blockIdx.x * 8 + (threadIdx.x >> 5);
    const int lane = threadIdx.x & 31;
    float acc = 0.f;
    for (int j = lane; j < Hd; j += 32) acc += Wo[(size_t)o * Hd + j] * bv[j];
    #pragma unroll
    for (int off = 16; off > 0; off >>= 1) acc += __shfl_xor_sync(0xffffffffu, acc, off);
    if (lane == 0) bc[o] = acc + bo[o];
}

// c = bq . bk
__global__ void cdot_kernel(const float* __restrict__ bq, const float* __restrict__ bk,
                            float* __restrict__ out)
{
    __shared__ float sh[8];
    const int tid = threadIdx.x, lane = tid & 31, warp = tid >> 5;
    float acc = 0.f;
    for (int i = tid; i < Hd; i += 256) acc += bq[i] * bk[i];
    #pragma unroll
    for (int off = 16; off > 0; off >>= 1) acc += __shfl_xor_sync(0xffffffffu, acc, off);
    if (lane == 0) sh[warp] = acc;
    __syncthreads();
    if (tid == 0) {
        float s = 0.f;
        #pragma unroll
        for (int i = 0; i < 8; i++) s += sh[i];
        out[0] = s;
    }
}

// -------------------- attention + modality-mean combine --------------------
// Per batch b: scores[m][n] = (f_m.P_n + w.f_m + u.f_n + c)/32 * conf[b,m]
// attn = softmax_n(scores); wgt[n] = mean_m attn[m][n]; g[b] = sum_n wgt[n]*f_n
__global__ void attn_kernel(const float* __restrict__ F, const float* __restrict__ P,
                            const float* __restrict__ conf,
                            const float* __restrict__ u, const float* __restrict__ w,
                            const float* __restrict__ cptr,
                            float* __restrict__ G)
{
    const int b    = blockIdx.x;
    const int tid  = threadIdx.x;   // 128 threads
    const int warp = tid >> 5;      // 0..3 : modality m
    const int lane = tid & 31;

    const float* fb = F + (size_t)b * (Mm * Hd);
    const float* pb = P + (size_t)b * (Mm * Hd);

    __shared__ float s_s[4][4];
    __shared__ float s_wf[4], s_uf[4], s_wgt[4];

    // warp m keeps f_m in registers
    float fr[32];
    const float* fm = fb + warp * Hd;
    #pragma unroll
    for (int j = 0; j < 32; j++) fr[j] = fm[lane + j * 32];

    // raw quadratic scores: f_m . P_n
    #pragma unroll
    for (int n = 0; n < 4; n++) {
        const float* pn = pb + n * Hd;
        float acc = 0.f;
        #pragma unroll
        for (int j = 0; j < 32; j++) acc += fr[j] * pn[lane + j * 32];
        #pragma unroll
        for (int off = 16; off > 0; off >>= 1) acc += __shfl_xor_sync(0xffffffffu, acc, off);
        if (lane == 0) s_s[warp][n] = acc;
    }
    // linear terms: w.f_m and u.f_m
    {
        float aw = 0.f, au = 0.f;
        #pragma unroll
        for (int j = 0; j < 32; j++) {
            aw += fr[j] * w[lane + j * 32];
            au += fr[j] * u[lane + j * 32];
        }
        #pragma unroll
        for (int off = 16; off > 0; off >>= 1) {
            aw += __shfl_xor_sync(0xffffffffu, aw, off);
            au += __shfl_xor_sync(0xffffffffu, au, off);
        }
        if (lane == 0) { s_wf[warp] = aw; s_uf[warp] = au; }
    }
    __syncthreads();

    // tiny 4x4 softmax, row m handled by thread m
    if (tid < 4) {
        const int m = tid;
        const float cf = conf[(size_t)b * 4 + m];
        const float c0 = cptr[0];
        float l[4];
        #pragma unroll
        for (int n = 0; n < 4; n++)
            l[n] = (s_s[m][n] + s_wf[m] + s_uf[n] + c0) * (1.f / 32.f) * cf;
        float mx = fmaxf(fmaxf(l[0], l[1]), fmaxf(l[2], l[3]));
        float e[4], sum = 0.f;
        #pragma unroll
        for (int n = 0; n < 4; n++) { e[n] = expf(l[n] - mx); sum += e[n]; }
        const float inv = 1.f / sum;
        #pragma unroll
        for (int n = 0; n < 4; n++) s_s[m][n] = e[n] * inv;  // overwrite with attn
    }
    __syncthreads();
    if (tid < 4)
        s_wgt[tid] = 0.25f * (s_s[0][tid] + s_s[1][tid] + s_s[2][tid] + s_s[3][tid]);
    __syncthreads();

    const float w0 = s_wgt[0], w1 = s_wgt[1], w2 = s_wgt[2], w3 = s_wgt[3];
    float* gb = G + (size_t)b * Hd;
    for (int h = tid; h < Hd; h += 128)
        gb[h] = w0 * fb[h] + w1 * fb[Hd + h] + w2 * fb[2 * Hd + h] + w3 * fb[3 * Hd + h];
}

// -------------------- launch --------------------
extern "C" void kernel_launch(void* const* d_in, const int* in_sizes, int n_in,
                              void* d_out, int out_size)
{
    const float* F    = (const float*)d_in[0];  // [B, M, H]
    const float* conf = (const float*)d_in[1];  // [B, M, 1]
    const float* Wq   = (const float*)d_in[2];
    const float* bq   = (const float*)d_in[3];
    const float* Wk   = (const float*)d_in[4];
    const float* bk   = (const float*)d_in[5];
    const float* Wv   = (const float*)d_in[6];
    const float* bv   = (const float*)d_in[7];
    const float* Wo   = (const float*)d_in[8];
    const float* bo   = (const float*)d_in[9];
    float* out = (float*)d_out;                 // [B, H]

    float *pA, *pWc, *pu, *pw, *pbc, *pc, *pP, *pG;
    cudaGetSymbolAddress((void**)&pA,  g_A);
    cudaGetSymbolAddress((void**)&pWc, g_Wc);
    cudaGetSymbolAddress((void**)&pu,  g_u);
    cudaGetSymbolAddress((void**)&pw,  g_w);
    cudaGetSymbolAddress((void**)&pbc, g_bc);
    cudaGetSymbolAddress((void**)&pc,  g_c);
    cudaGetSymbolAddress((void**)&pP,  g_P);
    cudaGetSymbolAddress((void**)&pG,  g_G);

    const dim3 blk(256);

    // 1) A = Wq^T Wk : C[o,h] = sum_j Wq[j,o]*Wk[j,h]   (TN: both K-strided)
    sgemm_kernel<false, false, false><<<dim3(Hd / BN, Hd / BM), blk>>>(Wq, Wk, pA, nullptr, Hd, Hd, Hd);

    // 2) Wc = Wo Wv : C[o,h] = sum_j Wo[o,j]*Wv[j,h]    (NN)
    sgemm_kernel<true, false, false><<<dim3(Hd / BN, Hd / BM), blk>>>(Wo, Wv, pWc, nullptr, Hd, Hd, Hd);

    // 3) u, w column sums; 4) bc; 5) c
    colsum_kernel<<<Hd / 256, 256>>>(Wk, bq, Wq, bk, pu, pw);
    bc_kernel<<<Hd / 8, 256>>>(Wo, bv, bo, pbc);
    cdot_kernel<<<1, 256>>>(bq, bk, pc);

    // 6) P = F2d @ A^T : C[i,o] = sum_h F[i,h]*A[o,h]   (NT) — 68.7 GFLOP main GEMM
    sgemm_kernel<true, true, false><<<dim3(Hd / BN, (Bn * Mm) / BM), blk>>>(F, pA, pP, nullptr, Bn * Mm, Hd, Hd);

    // 7) per-batch 4x4 attention + weighted feature mean -> G
    attn_kernel<<<Bn, 128>>>(F, pP, conf, pu, pw, pc, pG);

    // 8) out = G @ Wc^T + bc                            (NT) — 17.2 GFLOP
    sgemm_kernel<true, true, true><<<dim3(Hd / BN, Bn / BM), blk>>>(pG, pWc, out, pbc, Bn, Hd, Hd);
}

// round 17
// speedup vs baseline: 1.0010x; 1.0005x over previous
#include <cuda_runtime.h>

// Problem constants
static constexpr int Hd = 1024;   // hidden dim
static constexpr int Bn = 8192;   // batch
static constexpr int Mm = 4;      // modalities

// -------------------- device scratch (no allocation allowed) --------------------
__device__ float g_A [Hd * Hd];             // A  = Wq^T Wk            (4 MB)
__device__ float g_Wc[Hd * Hd];             // Wc = Wo Wv              (4 MB)
__device__ float g_u [Hd];                  // u[h] = sum_j bq[j] Wk[j,h]
__device__ float g_w [Hd];                  // w[o] = sum_j Wq[j,o] bk[j]
__device__ float g_bc[Hd];                  // bc   = Wo bv + bo
__device__ float g_c [1];                   // c    = bq . bk
__device__ float g_P [(size_t)Bn * Mm * Hd];// P[b,n,o] = sum_h A[o,h] f[b,n,h] (128 MB)
__device__ float g_G [(size_t)Bn * Hd];     // g[b,h]   = sum_n wgt[b,n] f[b,n,h] (32 MB)

// -------------------- generic SGEMM: C[m,n] = sum_k opA(m,k)*opB(n,k) --------------------
// opA(m,k) = A_KC ? A[m*K + k] : A[k*ldA + m]   (ldA passed as "ld")
// opB(n,k) = B_KC ? B[n*K + k] : B[k*ldB + n]
// Tiles: 128x128x16, 256 threads, 8x8 per thread, register-prefetch pipeline.
// All dims are multiples of 128 (M in {1024, 8192, 32768}, N=K=1024) -> no bounds checks.

static constexpr int BM = 128, BN = 128, BK = 16, PAD = 4;

template<bool KC>
__device__ __forceinline__ void tile_load(const float* __restrict__ g,
                                          int base, int K, int ld, int k0,
                                          int tid, float (&r)[8])
{
    if (KC) {
        // rows are K-contiguous: float4 along K
        const int k4  = tid & 3;     // which float4 of the 16 k's
        const int row = tid >> 2;    // 0..63
        const float* p = g + (size_t)(base + row) * K + k0 + k4 * 4;
        float4 v0 = *reinterpret_cast<const float4*>(p);
        float4 v1 = *reinterpret_cast<const float4*>(p + (size_t)64 * K);
        r[0] = v0.x; r[1] = v0.y; r[2] = v0.z; r[3] = v0.w;
        r[4] = v1.x; r[5] = v1.y; r[6] = v1.z; r[7] = v1.w;
    } else {
        // K is strided (row = k): float4 along m/n
        const int kk = tid >> 4;     // 0..15
        const int c4 = tid & 15;     // 0..15
        const float* p = g + (size_t)(k0 + kk) * ld + base + c4 * 4;
        float4 v0 = *reinterpret_cast<const float4*>(p);
        float4 v1 = *reinterpret_cast<const float4*>(p + 64);
        r[0] = v0.x; r[1] = v0.y; r[2] = v0.z; r[3] = v0.w;
        r[4] = v1.x; r[5] = v1.y; r[6] = v1.z; r[7] = v1.w;
    }
}

template<bool KC>
__device__ __forceinline__ void tile_store(float (&S)[BK][BM + PAD],
                                           int tid, const float (&r)[8])
{
    if (KC) {
        const int k4  = tid & 3;
        const int row = tid >> 2;
        #pragma unroll
        for (int c = 0; c < 4; c++) {
            S[k4 * 4 + c][row]      = r[c];
            S[k4 * 4 + c][row + 64] = r[4 + c];
        }
    } else {
        const int kk = tid >> 4;
        const int c4 = tid & 15;
        *reinterpret_cast<float4*>(&S[kk][c4 * 4])      = make_float4(r[0], r[1], r[2], r[3]);
        *reinterpret_cast<float4*>(&S[kk][64 + c4 * 4]) = make_float4(r[4], r[5], r[6], r[7]);
    }
}

__device__ __forceinline__ void mk_compute(const float (&As)[BK][BM + PAD],
                                           const float (&Bs)[BK][BN + PAD],
                                           float (&acc)[8][8], int ty, int tx)
{
    #pragma unroll
    for (int kk = 0; kk < BK; kk++) {
        float af[8], bf[8];
        *reinterpret_cast<float4*>(&af[0]) = *reinterpret_cast<const float4*>(&As[kk][ty * 8]);
        *reinterpret_cast<float4*>(&af[4]) = *reinterpret_cast<const float4*>(&As[kk][ty * 8 + 4]);
        *reinterpret_cast<float4*>(&bf[0]) = *reinterpret_cast<const float4*>(&Bs[kk][tx * 8]);
        *reinterpret_cast<float4*>(&bf[4]) = *reinterpret_cast<const float4*>(&Bs[kk][tx * 8 + 4]);
        #pragma unroll
        for (int i = 0; i < 8; i++)
            #pragma unroll
            for (int j = 0; j < 8; j++)
                acc[i][j] += af[i] * bf[j];
    }
}

template<bool A_KC, bool B_KC, bool BIAS>
__global__ __launch_bounds__(256, 2)
void sgemm_kernel(const float* __restrict__ Ag, const float* __restrict__ Bg,
                  float* __restrict__ Cg, const float* __restrict__ bias,
                  int M, int N, int K)
{
    __shared__ float As[BK][BM + PAD];
    __shared__ float Bs[BK][BN + PAD];

    const int tid = threadIdx.x;
    const int tx  = tid & 15;   // n-direction
    const int ty  = tid >> 4;   // m-direction
    const int m0  = blockIdx.y * BM;
    const int n0  = blockIdx.x * BN;

    float acc[8][8];
    #pragma unroll
    for (int i = 0; i < 8; i++)
        #pragma unroll
        for (int j = 0; j < 8; j++) acc[i][j] = 0.f;

    float ra[8], rb[8];

    // prologue: tile 0
    tile_load<A_KC>(Ag, m0, K, M, 0, tid, ra);
    tile_load<B_KC>(Bg, n0, K, N, 0, tid, rb);
    tile_store<A_KC>(As, tid, ra);
    tile_store<B_KC>(Bs, tid, rb);
    __syncthreads();

    for (int k0 = BK; k0 < K; k0 += BK) {
        // prefetch next tile to registers
        tile_load<A_KC>(Ag, m0, K, M, k0, tid, ra);
        tile_load<B_KC>(Bg, n0, K, N, k0, tid, rb);
        // compute on current smem tile
        mk_compute(As, Bs, acc, ty, tx);
        __syncthreads();
        tile_store<A_KC>(As, tid, ra);
        tile_store<B_KC>(Bs, tid, rb);
        __syncthreads();
    }
    mk_compute(As, Bs, acc, ty, tx);

    // epilogue
    float bz[8];
    #pragma unroll
    for (int j = 0; j < 8; j++)
        bz[j] = BIAS ? bias[n0 + tx * 8 + j] : 0.f;

    #pragma unroll
    for (int i = 0; i < 8; i++) {
        float* cp = Cg + (size_t)(m0 + ty * 8 + i) * N + n0 + tx * 8;
        float4 o0 = make_float4(acc[i][0] + bz[0], acc[i][1] + bz[1],
                                acc[i][2] + bz[2], acc[i][3] + bz[3]);
        float4 o1 = make_float4(acc[i][4] + bz[4], acc[i][5] + bz[5],
                                acc[i][6] + bz[6], acc[i][7] + bz[7]);
        *reinterpret_cast<float4*>(cp)     = o0;
        *reinterpret_cast<float4*>(cp + 4) = o1;
    }
}

// -------------------- small precompute kernels --------------------

// u[h] = sum_j bq[j]*Wk[j,h] ; w[h] = sum_j bk[j]*Wq[j,h]   (coalesced column sums)
__global__ void colsum_kernel(const float* __restrict__ Wk, const float* __restrict__ bq,
                              const float* __restrict__ Wq, const float* __restrict__ bk,
                              float* __restrict__ u, float* __restrict__ w)
{
    const int h = blockIdx.x * blockDim.x + threadIdx.x;
    float su = 0.f, sw = 0.f;
    for (int j = 0; j < Hd; j++) {
        su += bq[j] * Wk[(size_t)j * Hd + h];
        sw += bk[j] * Wq[(size_t)j * Hd + h];
    }
    u[h] = su;
    w[h] = sw;
}

// bc[o] = sum_j Wo[o,j]*bv[j] + bo[o]   (warp per row)
__global__ void bc_kernel(const float* __restrict__ Wo, const float* __restrict__ bv,
                          const float* __restrict__ bo, float* __restrict__ bc)
{
    const int o    = blockIdx.x * 8 + (threadIdx.x >> 5);
    const int lane = threadIdx.x & 31;
    float acc = 0.f;
    for (int j = lane; j < Hd; j += 32) acc += Wo[(size_t)o * Hd + j] * bv[j];
    #pragma unroll
    for (int off = 16; off > 0; off >>= 1) acc += __shfl_xor_sync(0xffffffffu, acc, off);
    if (lane == 0) bc[o] = acc + bo[o];
}

// c = bq . bk
__global__ void cdot_kernel(const float* __restrict__ bq, const float* __restrict__ bk,
                            float* __restrict__ out)
{
    __shared__ float sh[8];
    const int tid = threadIdx.x, lane = tid & 31, warp = tid >> 5;
    float acc = 0.f;
    for (int i = tid; i < Hd; i += 256) acc += bq[i] * bk[i];
    #pragma unroll
    for (int off = 16; off > 0; off >>= 1) acc += __shfl_xor_sync(0xffffffffu, acc, off);
    if (lane == 0) sh[warp] = acc;
    __syncthreads();
    if (tid == 0) {
        float s = 0.f;
        #pragma unroll
        for (int i = 0; i < 8; i++) s += sh[i];
        out[0] = s;
    }
}

// -------------------- attention + modality-mean combine --------------------
// Per batch b: scores[m][n] = (f_m.P_n + w.f_m + u.f_n + c)/32 * conf[b,m]
// attn = softmax_n(scores); wgt[n] = mean_m attn[m][n]; g[b] = sum_n wgt[n]*f_n
__global__ void attn_kernel(const float* __restrict__ F, const float* __restrict__ P,
                            const float* __restrict__ conf,
                            const float* __restrict__ u, const float* __restrict__ w,
                            const float* __restrict__ cptr,
                            float* __restrict__ G)
{
    const int b    = blockIdx.x;
    const int tid  = threadIdx.x;   // 128 threads
    const int warp = tid >> 5;      // 0..3 : modality m
    const int lane = tid & 31;

    const float* fb = F + (size_t)b * (Mm * Hd);
    const float* pb = P + (size_t)b * (Mm * Hd);

    __shared__ float s_s[4][4];
    __shared__ float s_wf[4], s_uf[4], s_wgt[4];

    // warp m keeps f_m in registers
    float fr[32];
    const float* fm = fb + warp * Hd;
    #pragma unroll
    for (int j = 0; j < 32; j++) fr[j] = fm[lane + j * 32];

    // raw quadratic scores: f_m . P_n
    #pragma unroll
    for (int n = 0; n < 4; n++) {
        const float* pn = pb + n * Hd;
        float acc = 0.f;
        #pragma unroll
        for (int j = 0; j < 32; j++) acc += fr[j] * pn[lane + j * 32];
        #pragma unroll
        for (int off = 16; off > 0; off >>= 1) acc += __shfl_xor_sync(0xffffffffu, acc, off);
        if (lane == 0) s_s[warp][n] = acc;
    }
    // linear terms: w.f_m and u.f_m
    {
        float aw = 0.f, au = 0.f;
        #pragma unroll
        for (int j = 0; j < 32; j++) {
            aw += fr[j] * w[lane + j * 32];
            au += fr[j] * u[lane + j * 32];
        }
        #pragma unroll
        for (int off = 16; off > 0; off >>= 1) {
            aw += __shfl_xor_sync(0xffffffffu, aw, off);
            au += __shfl_xor_sync(0xffffffffu, au, off);
        }
        if (lane == 0) { s_wf[warp] = aw; s_uf[warp] = au; }
    }
    __syncthreads();

    // tiny 4x4 softmax, row m handled by thread m
    if (tid < 4) {
        const int m = tid;
        const float cf = conf[(size_t)b * 4 + m];
        const float c0 = cptr[0];
        float l[4];
        #pragma unroll
        for (int n = 0; n < 4; n++)
            l[n] = (s_s[m][n] + s_wf[m] + s_uf[n] + c0) * (1.f / 32.f) * cf;
        float mx = fmaxf(fmaxf(l[0], l[1]), fmaxf(l[2], l[3]));
        float e[4], sum = 0.f;
        #pragma unroll
        for (int n = 0; n < 4; n++) { e[n] = expf(l[n] - mx); sum += e[n]; }
        const float inv = 1.f / sum;
        #pragma unroll
        for (int n = 0; n < 4; n++) s_s[m][n] = e[n] * inv;  // overwrite with attn
    }
    __syncthreads();
    if (tid < 4)
        s_wgt[tid] = 0.25f * (s_s[0][tid] + s_s[1][tid] + s_s[2][tid] + s_s[3][tid]);
    __syncthreads();

    const float w0 = s_wgt[0], w1 = s_wgt[1], w2 = s_wgt[2], w3 = s_wgt[3];
    float* gb = G + (size_t)b * Hd;
    for (int h = tid; h < Hd; h += 128)
        gb[h] = w0 * fb[h] + w1 * fb[Hd + h] + w2 * fb[2 * Hd + h] + w3 * fb[3 * Hd + h];
}

// -------------------- launch --------------------
extern "C" void kernel_launch(void* const* d_in, const int* in_sizes, int n_in,
                              void* d_out, int out_size)
{
    const float* F    = (const float*)d_in[0];  // [B, M, H]
    const float* conf = (const float*)d_in[1];  // [B, M, 1]
    const float* Wq   = (const float*)d_in[2];
    const float* bq   = (const float*)d_in[3];
    const float* Wk   = (const float*)d_in[4];
    const float* bk   = (const float*)d_in[5];
    const float* Wv   = (const float*)d_in[6];
    const float* bv   = (const float*)d_in[7];
    const float* Wo   = (const float*)d_in[8];
    const float* bo   = (const float*)d_in[9];
    float* out = (float*)d_out;                 // [B, H]

    float *pA, *pWc, *pu, *pw, *pbc, *pc, *pP, *pG;
    cudaGetSymbolAddress((void**)&pA,  g_A);
    cudaGetSymbolAddress((void**)&pWc, g_Wc);
    cudaGetSymbolAddress((void**)&pu,  g_u);
    cudaGetSymbolAddress((void**)&pw,  g_w);
    cudaGetSymbolAddress((void**)&pbc, g_bc);
    cudaGetSymbolAddress((void**)&pc,  g_c);
    cudaGetSymbolAddress((void**)&pP,  g_P);
    cudaGetSymbolAddress((void**)&pG,  g_G);

    const dim3 blk(256);

    // 1) A = Wq^T Wk : C[o,h] = sum_j Wq[j,o]*Wk[j,h]   (TN: both K-strided)
    sgemm_kernel<false, false, false><<<dim3(Hd / BN, Hd / BM), blk>>>(Wq, Wk, pA, nullptr, Hd, Hd, Hd);

    // 2) Wc = Wo Wv : C[o,h] = sum_j Wo[o,j]*Wv[j,h]    (NN)
    sgemm_kernel<true, false, false><<<dim3(Hd / BN, Hd / BM), blk>>>(Wo, Wv, pWc, nullptr, Hd, Hd, Hd);

    // 3) u, w column sums; 4) bc; 5) c
    colsum_kernel<<<Hd / 256, 256>>>(Wk, bq, Wq, bk, pu, pw);
    bc_kernel<<<Hd / 8, 256>>>(Wo, bv, bo, pbc);
    cdot_kernel<<<1, 256>>>(bq, bk, pc);

    // 6) P = F2d @ A^T : C[i,o] = sum_h F[i,h]*A[o,h]   (NT) — 68.7 GFLOP main GEMM
    sgemm_kernel<true, true, false><<<dim3(Hd / BN, (Bn * Mm) / BM), blk>>>(F, pA, pP, nullptr, Bn * Mm, Hd, Hd);

    // 7) per-batch 4x4 attention + weighted feature mean -> G
    attn_kernel<<<Bn, 128>>>(F, pP, conf, pu, pw, pc, pG);

    // 8) out = G @ Wc^T + bc                            (NT) — 17.2 GFLOP
    sgemm_kernel<true, true, true><<<dim3(Hd / BN, Bn / BM), blk>>>(pG, pWc, out, pbc, Bn, Hd, Hd);
}